// round 6
// baseline (speedup 1.0000x reference)
#include <cuda_runtime.h>
#include <cmath>

#define TOKS 4096          // B_SZ * L
#define DD   1024          // D
#define NN   16            // N
#define ROWF ((2*DD + 1) * NN)   // 32784 floats per token in output

// 1/A table (no cudaMalloc allowed)
__device__ float g_R[DD * NN];

__global__ void init_R_kernel(const float* __restrict__ A)
{
    int i = blockIdx.x * blockDim.x + threadIdx.x;
    if (i < DD * NN) g_R[i] = __frcp_rn(A[i]);
}

__device__ __forceinline__ float softplus_f(float z) {
    // matches jax.nn.softplus: max(z,0) + log1p(exp(-|z|))
    return fmaxf(z, 0.f) + log1pf(__expf(-fabsf(z)));
}

// ---------------------------------------------------------------------------
// Fused persistent kernel. Per token:
//   phase A (proj): warp w computes dot(x, W_row) for rows 2w, 2w+1 (warp 15
//     also the delta row). Rows are fixed per warp -> W slices stay L1-hot.
//     Butterfly-reduce, lane 0 drops results into 132 B of smem.
//   phase B (expand): thread t handles d = t and t+512; softplus once per d;
//     A_bar = exp(Delta*A[d,n]); deltaB_x = (A_bar-1)*R[d,n]*B[n]*x[d]
//     (Delta cancels in B_bar). 2 KB-contiguous streaming stores per warp.
// Proj math of token i+1 overlaps the store drain of token i.
// ---------------------------------------------------------------------------
__global__ __launch_bounds__(512, 3) void fused_kernel(
    const float* __restrict__ x,  const float* __restrict__ Wb,
    const float* __restrict__ Wc, const float* __restrict__ Wd,
    const float* __restrict__ A,  const float* __restrict__ dparam,
    float* __restrict__ out)
{
    __shared__ float sB[NN];
    __shared__ float sC[NN];
    __shared__ float sS;

    const int tid  = threadIdx.x;
    const int wid  = tid >> 5;
    const int lane = tid & 31;

    // this warp's weight rows (constant across tokens -> L1-resident)
    const int r0 = 2 * wid, r1 = 2 * wid + 1;
    const float4* w0 = (const float4*)((r0 < 16) ? (Wb + r0 * DD) : (Wc + (r0 - 16) * DD));
    const float4* w1 = (const float4*)((r1 < 16) ? (Wb + r1 * DD) : (Wc + (r1 - 16) * DD));
    const float4* w2 = (const float4*)Wd;

    for (int tok = blockIdx.x; tok < TOKS; tok += gridDim.x) {
        const float4* x4 = (const float4*)(x + (size_t)tok * DD);
        float* ob = out + (size_t)tok * ROWF;

        // ---------------- phase A: projections ----------------
        float a0 = 0.f, a1 = 0.f, a2 = 0.f;
#pragma unroll
        for (int i = 0; i < 8; i++) {
            float4 xv = __ldg(x4 + i * 32 + lane);
            float4 v0 = __ldg(w0 + i * 32 + lane);
            float4 v1 = __ldg(w1 + i * 32 + lane);
            a0 = fmaf(xv.x, v0.x, fmaf(xv.y, v0.y, fmaf(xv.z, v0.z, fmaf(xv.w, v0.w, a0))));
            a1 = fmaf(xv.x, v1.x, fmaf(xv.y, v1.y, fmaf(xv.z, v1.z, fmaf(xv.w, v1.w, a1))));
            if (wid == 15) {
                float4 v2 = __ldg(w2 + i * 32 + lane);
                a2 = fmaf(xv.x, v2.x, fmaf(xv.y, v2.y, fmaf(xv.z, v2.z, fmaf(xv.w, v2.w, a2))));
            }
        }
#pragma unroll
        for (int o = 16; o > 0; o >>= 1) {
            a0 += __shfl_xor_sync(0xffffffffu, a0, o);
            a1 += __shfl_xor_sync(0xffffffffu, a1, o);
            a2 += __shfl_xor_sync(0xffffffffu, a2, o);
        }
        if (lane == 0) {
            if (r0 < 16) sB[r0] = a0; else sC[r0 - 16] = a0;
            if (r1 < 16) sB[r1] = a1; else sC[r1 - 16] = a1;
            if (wid == 15) sS = a2;
        }
        __syncthreads();

        // C row: 64 B, 4 threads
        if (tid < 4)
            __stcs((float4*)(ob + 2 * DD * NN) + tid, ((const float4*)sC)[tid]);

        // ---------------- phase B: expansion ----------------
        const float s = sS;
#pragma unroll
        for (int half = 0; half < 2; half++) {
            int d = tid + half * 512;
            float Delta = softplus_f(s + __ldg(dparam + d));
            float xd    = __ldg(x + (size_t)tok * DD + d);   // L1 hit (just read)
            const float4* A4 = (const float4*)A   + (size_t)d * 4;
            const float4* R4 = (const float4*)g_R + (size_t)d * 4;
#pragma unroll
            for (int g = 0; g < 4; g++) {
                float4 a  = __ldg(A4 + g);
                float4 r  = __ldg(R4 + g);
                float4 Bg = ((const float4*)sB)[g];
                float4 eo, bo;
#define COMP(f)                                                              \
                {                                                            \
                    float dA = Delta * a.f;                                  \
                    float e  = __expf(dA);                                   \
                    float em1 = (fabsf(dA) < 0.015625f)                      \
                        ? dA * fmaf(dA, fmaf(dA, 0.16666667f, 0.5f), 1.f)    \
                        : (e - 1.f);                                         \
                    eo.f = e;                                                \
                    bo.f = em1 * (r.f * (Bg.f * xd));                        \
                }
                COMP(x) COMP(y) COMP(z) COMP(w)
#undef COMP
                __stcs((float4*)ob + (size_t)d * 4 + g, eo);
                __stcs((float4*)ob + (size_t)DD * 4 + (size_t)d * 4 + g, bo);
            }
        }
        __syncthreads();   // smem (sB/sC/sS) reusable for next token
    }
}

// ---------------------------------------------------------------------------
extern "C" void kernel_launch(void* const* d_in, const int* in_sizes, int n_in,
                              void* d_out, int out_size)
{
    const float* x  = (const float*)d_in[0];
    const float* Wb = (const float*)d_in[1];
    const float* Wc = (const float*)d_in[2];
    const float* Wd = (const float*)d_in[3];
    const float* A  = (const float*)d_in[4];
    const float* dp = (const float*)d_in[5];
    float* out = (float*)d_out;

    init_R_kernel<<<32, 512>>>(A);                       // 16K rcp, ~2 us
    fused_kernel<<<456, 512>>>(x, Wb, Wc, Wd, A, dp, out);
}

// round 7
// speedup vs baseline: 2.6605x; 2.6605x over previous
#include <cuda_runtime.h>
#include <cmath>

#define TOKS 4096          // B_SZ * L
#define DD   1024          // D
#define NN   16            // N
#define ROWF ((2*DD + 1) * NN)   // 32784 floats per token in output

// scratch (no cudaMalloc allowed)
__device__ float g_B[TOKS][NN];
__device__ float g_C[TOKS][NN];
__device__ float g_s[TOKS];
__device__ float g_R[DD * NN];        // 1 / A

__device__ __forceinline__ float softplus_f(float z) {
    // matches jax.nn.softplus: max(z,0) + log1p(exp(-|z|))
    return fmaxf(z, 0.f) + log1pf(__expf(-fabsf(z)));
}

// ---------------------------------------------------------------------------
// Phase 1: projections only. B = x@Wb^T, C = x@Wc^T, s = x@Wd^T.
// Weights staged in shared (132 KB); one warp per token PAIR (t, t+2048).
// Block 0 additionally builds the 1/A table (used by phase 2).
// ---------------------------------------------------------------------------
__global__ __launch_bounds__(512) void proj_kernel(
    const float* __restrict__ x, const float* __restrict__ Wb,
    const float* __restrict__ Wc, const float* __restrict__ Wd,
    const float* __restrict__ A)
{
    extern __shared__ float4 sw[];   // 33 * 256 float4 = 135168 B
    for (int i = threadIdx.x; i < 33 * 256; i += blockDim.x) {
        int j = i >> 8, c = i & 255;
        float4 v;
        if (j < 16)      v = ((const float4*)Wb)[j * 256 + c];
        else if (j < 32) v = ((const float4*)Wc)[(j - 16) * 256 + c];
        else             v = ((const float4*)Wd)[c];
        sw[i] = v;
    }
    if (blockIdx.x == 0) {           // one-time 1/A table
        for (int i = threadIdx.x; i < DD * NN; i += blockDim.x)
            g_R[i] = __frcp_rn(A[i]);
    }
    __syncthreads();

    int wg   = (blockIdx.x * blockDim.x + threadIdx.x) >> 5;  // 0..2047
    int lane = threadIdx.x & 31;
    int t0 = wg, t1 = wg + TOKS / 2;
    const float4* x0 = (const float4*)(x + (size_t)t0 * DD);
    const float4* x1 = (const float4*)(x + (size_t)t1 * DD);

    float acc0[33], acc1[33];
#pragma unroll
    for (int j = 0; j < 33; j++) { acc0[j] = 0.f; acc1[j] = 0.f; }

#pragma unroll
    for (int it = 0; it < 8; it++) {
        int c = it * 32 + lane;              // float4 index 0..255
        float4 a = __ldg(x0 + c);
        float4 b = __ldg(x1 + c);
#pragma unroll
        for (int j = 0; j < 33; j++) {
            float4 w = sw[j * 256 + c];
            acc0[j] = fmaf(a.x, w.x, fmaf(a.y, w.y, fmaf(a.z, w.z, fmaf(a.w, w.w, acc0[j]))));
            acc1[j] = fmaf(b.x, w.x, fmaf(b.y, w.y, fmaf(b.z, w.z, fmaf(b.w, w.w, acc1[j]))));
        }
    }

#pragma unroll
    for (int j = 0; j < 33; j++) {
#pragma unroll
        for (int o = 16; o > 0; o >>= 1) {
            acc0[j] += __shfl_xor_sync(0xffffffffu, acc0[j], o);
            acc1[j] += __shfl_xor_sync(0xffffffffu, acc1[j], o);
        }
    }

    if (lane == 0) {
#pragma unroll
        for (int j = 0; j < 16; j++) { g_B[t0][j] = acc0[j];      g_B[t1][j] = acc1[j]; }
#pragma unroll
        for (int j = 0; j < 16; j++) { g_C[t0][j] = acc0[16 + j]; g_C[t1][j] = acc1[16 + j]; }
        g_s[t0] = acc0[32];
        g_s[t1] = acc1[32];
    }
}

// ---------------------------------------------------------------------------
// Phase 2: expansion + 537 MB streaming stores (round-5 hot loop, proven).
// New: per-token smem stage computes Delta = softplus(s + dp[d]) ONCE per d
// (and stages the x row), removing the 32 MB g_Delta round-trip while keeping
// the hot loop lean. smem = 8.2 KB -> still 3 CTAs/SM.
//   A_bar    = exp(Delta * A[d,n])
//   deltaB_x = (A_bar - 1) * R[d,n] * B[tok,n] * x[tok,d]   (Delta cancels)
// ---------------------------------------------------------------------------
__global__ __launch_bounds__(512, 3) void ssm_kernel(
    const float* __restrict__ x, const float* __restrict__ A,
    const float* __restrict__ dparam, float* __restrict__ out)
{
    __shared__ float sD[DD];   // Delta per d
    __shared__ float sX[DD];   // x row

    const int tid = threadIdx.x;
    const int q   = tid & 3;    // n-quad 0..3
    const int dof = tid >> 2;   // 0..127
    const float4* A4 = (const float4*)A;
    const float4* R4 = (const float4*)g_R;

    for (int tok = blockIdx.x; tok < TOKS; tok += gridDim.x) {
        const float s = g_s[tok];
        float4 Bq = *((const float4*)g_B[tok] + q);
        const float* xr = x + (size_t)tok * DD;
        float* ob = out + (size_t)tok * ROWF;

        // stage Delta (1 softplus per d) and the x row
#pragma unroll
        for (int h = 0; h < 2; h++) {
            int d = tid + h * 512;
            sD[d] = softplus_f(s + __ldg(dparam + d));
            sX[d] = __ldg(xr + d);
        }
        __syncthreads();

        if (tid < 4)
            __stcs((float4*)(ob + 2 * DD * NN) + tid,
                   *((const float4*)g_C[tok] + tid));

#pragma unroll
        for (int it = 0; it < 8; it++) {
            int d = dof + it * 128;
            float Delta = sD[d];
            float xd    = sX[d];
            float4 a = __ldg(A4 + d * 4 + q);
            float4 r = __ldg(R4 + d * 4 + q);
            float4 eo, bo;
#define COMP(f)                                                              \
            {                                                                \
                float dA = Delta * a.f;                                      \
                float e  = __expf(dA);                                       \
                float em1 = (fabsf(dA) < 0.015625f)                          \
                    ? dA * fmaf(dA, fmaf(dA, 0.16666667f, 0.5f), 1.f)        \
                    : (e - 1.f);                                             \
                eo.f = e;                                                    \
                bo.f = em1 * (r.f * (Bq.f * xd));                            \
            }
            COMP(x) COMP(y) COMP(z) COMP(w)
#undef COMP
            __stcs((float4*)ob + (size_t)d * 4 + q, eo);
            __stcs((float4*)ob + (size_t)DD * 4 + (size_t)d * 4 + q, bo);
        }
        __syncthreads();   // sD/sX reused next token
    }
}

// ---------------------------------------------------------------------------
extern "C" void kernel_launch(void* const* d_in, const int* in_sizes, int n_in,
                              void* d_out, int out_size)
{
    const float* x  = (const float*)d_in[0];
    const float* Wb = (const float*)d_in[1];
    const float* Wc = (const float*)d_in[2];
    const float* Wd = (const float*)d_in[3];
    const float* A  = (const float*)d_in[4];
    const float* dp = (const float*)d_in[5];
    float* out = (float*)d_out;

    const int SMEM1 = 33 * 256 * 16;                   // 135168 B
    cudaFuncSetAttribute(proj_kernel, cudaFuncAttributeMaxDynamicSharedMemorySize, SMEM1);

    // Phase 1: projections (+1/A table), lean
    proj_kernel<<<128, 512, SMEM1>>>(x, Wb, Wc, Wd, A);
    // Phase 2: 3 CTAs/SM, grid-strided tokens, softplus staged in smem
    ssm_kernel<<<456, 512>>>(x, A, dp, out);
}